// round 9
// baseline (speedup 1.0000x reference)
#include <cuda_runtime.h>
#include <math.h>

#define W 512
#define F 257
#define HOP 128
#define FT 4
#define MAXT 1300
#define SPAN (W + (FT - 1) * HOP)   // 896

typedef unsigned long long ull;

__device__ __forceinline__ float ex2(float x) {
    float r; asm("ex2.approx.ftz.f32 %0, %1;" : "=f"(r) : "f"(x)); return r;
}
__device__ __forceinline__ float lg2(float x) {
    float r; asm("lg2.approx.ftz.f32 %0, %1;" : "=f"(r) : "f"(x)); return r;
}
__device__ __forceinline__ ull pack2(float lo, float hi) {
    ull r; asm("mov.b64 %0, {%1, %2};" : "=l"(r) : "f"(lo), "f"(hi)); return r;
}
__device__ __forceinline__ void unpack2(ull v, float &lo, float &hi) {
    asm("mov.b64 {%0, %1}, %2;" : "=f"(lo), "=f"(hi) : "l"(v));
}
__device__ __forceinline__ void ffma2(ull &acc, ull a, ull b) {
    asm("fma.rn.f32x2 %0, %1, %2, %0;" : "+l"(acc) : "l"(a), "l"(b));
}

// ---- static device scratch ----
struct Ctl { double acc; unsigned int pmaxi; unsigned int done; };
__device__ Ctl   g_ctl;
__device__ float g_bark[F], g_dshift[F], g_athpow[F];
__device__ float g_pr  [MAXT * F];
__device__ float g_pdel[MAXT * F];

// ---------------------------------------------------------------------------
// Mega STFT kernel. blockIdx.y: 0/1 = DFT parity CTAs, 2 = bin256 + tables.
// ---------------------------------------------------------------------------
__global__ void __launch_bounds__(128) stft_kernel(
    const float* __restrict__ xadv, const float* __restrict__ xref,
    int T, int Lv)
{
    int tid = threadIdx.x;
    int par = blockIdx.y;
    int t0  = blockIdx.x * FT;

    if (par == 2) {
        // ---- bin 256 (one warp per frame) + constant tables (CTA x==0) ----
        int wid = tid >> 5, l = tid & 31;
        int t = t0 + wid;
        float Pr = 0.f;
        if (t < T) {
            int base = t * HOP;
            float rr = 0.f, rd = 0.f;
            for (int n = l; n < 512; n += 32) {
                float hw = 0.5f - 0.5f * cospif((float)n * (1.f / 256.f));
                if (n & 1) hw = -hw;
                float r = xref[base + n], a = xadv[base + n];
                rr = fmaf(hw, r, rr);
                rd = fmaf(hw, a - r, rd);
            }
#pragma unroll
            for (int o = 16; o > 0; o >>= 1) {
                rr += __shfl_xor_sync(0xFFFFFFFFu, rr, o);
                rd += __shfl_xor_sync(0xFFFFFFFFu, rd, o);
            }
            const float gw2 = 1.0172526041666667e-5f;
            Pr = gw2 * rr * rr;
            if (l == 0) {
                g_pr[t * F + 256]   = Pr;
                g_pdel[t * F + 256] = gw2 * rd * rd;
                atomicMax(&g_ctl.pmaxi, __float_as_uint(Pr));
            }
        }
        if (blockIdx.x == 0) {
            for (int i = tid; i < F; i += 128) {
                double freq = (double)i * (8000.0 / 256.0);
                double bark = 13.0 * atan(0.00076 * freq)
                            + 3.5  * atan((freq / 7500.0) * (freq / 7500.0));
                float bf = (float)bark;
                g_bark[i]   = bf;
                g_dshift[i] = -6.025f - 0.275f * bf;
                if (freq >= 20.0 && freq <= 20000.0) {
                    double fk = freq * 0.001;
                    double ath = 3.64 * pow(fk, -0.8)
                               - 6.5  * exp(-0.6 * (fk - 3.3) * (fk - 3.3))
                               + 0.001 * fk * fk * fk * fk
                               - 12.0;
                    g_athpow[i] = exp10f((float)ath * 0.1f);
                } else {
                    g_athpow[i] = 0.0f;
                }
            }
        }
        return;
    }

    // ---- folded real DFT ----
    __shared__ float      xr[SPAN], xd[SPAN];
    __shared__ ulonglong2 eo[FT][128];      // (e_ref,e_del) , (o_ref,o_del)
    __shared__ float      edge[FT][6];
    __shared__ ulonglong2 tw[544];          // ((c,c),(s,s)); idx k+(k>>4)
    __shared__ float      wmax[4];

    int base = t0 * HOP;

    for (int k = tid; k < 512; k += 128) {
        float s, c;
        sincospif((float)k * (1.f / 256.f), &s, &c);
        int pk = k + (k >> 4);
        ulonglong2 u; u.x = pack2(c, c); u.y = pack2(s, s);
        tw[pk] = u;
    }
    for (int i = tid; i < SPAN; i += 128) {
        int g = base + i;
        float r = 0.f, d = 0.f;
        if (g < Lv) { r = xref[g]; d = xadv[g] - r; }
        xr[i] = r; xd[i] = d;
    }
    __syncthreads();

    float s = par ? -1.f : 1.f;
    for (int idx = tid; idx < FT * 128; idx += 128) {
        int j = idx >> 7, n = idx & 127;
        const float* fr = xr + j * HOP;
        const float* fd = xd + j * HOP;
        if (n == 0) {
            edge[j][0] = fr[256];
            edge[j][1] = (fr[128] + fr[384]) * 0.5f;
            edge[j][2] = (fr[128] - fr[384]) * 0.5f;
            edge[j][3] = fd[256];
            edge[j][4] = (fd[128] + fd[384]) * 0.5f;
            edge[j][5] = (fd[128] - fd[384]) * 0.5f;
        } else {
            float h1 = 0.5f - 0.5f * cospif((float)n * (1.f / 256.f));
            float h2 = 0.5f - 0.5f * cospif((float)(256 - n) * (1.f / 256.f));
            float a1 = fr[n], a2 = fr[512 - n], a3 = fr[256 - n], a4 = fr[256 + n];
            float b1 = fd[n], b2 = fd[512 - n], b3 = fd[256 - n], b4 = fd[256 + n];
            float er = (a1 + a2) * h1 + s * ((a3 + a4) * h2);
            float orf = (a1 - a2) * h1 - s * ((a3 - a4) * h2);
            float ed = (b1 + b2) * h1 + s * ((b3 + b4) * h2);
            float od = (b1 - b2) * h1 - s * ((b3 - b4) * h2);
            ulonglong2 u;
            u.x = pack2(er, ed);
            u.y = pack2(orf, od);
            eo[j][n] = u;
        }
    }
    __syncthreads();

    int f = 2 * tid + par;
    float sgn = (tid & 1) ? -1.f : 1.f;
    ull accR[FT], accI[FT];
#pragma unroll
    for (int j = 0; j < FT; j++) {
        if (par == 0) {
            accR[j] = pack2(fmaf(sgn, edge[j][1], edge[j][0]),
                            fmaf(sgn, edge[j][4], edge[j][3]));
            accI[j] = pack2(0.f, 0.f);
        } else {
            accR[j] = pack2(-edge[j][0], -edge[j][3]);
            accI[j] = pack2(sgn * edge[j][2], sgn * edge[j][5]);
        }
    }
    int k = f;
#pragma unroll 4
    for (int n = 1; n < 128; n++) {
        ulonglong2 cs = tw[k + (k >> 4)];
#pragma unroll
        for (int j = 0; j < FT; j++) {
            ulonglong2 v = eo[j][n];
            ffma2(accR[j], v.x, cs.x);
            ffma2(accI[j], v.y, cs.y);
        }
        k = (k + f) & 511;
    }
    const float gw2 = 1.0172526041666667e-5f;   // (8/3)/512^2
    float lmax = 0.f;
#pragma unroll
    for (int j = 0; j < FT; j++) {
        int t = t0 + j;
        if (t < T) {
            float rr, rd, ii, id_;
            unpack2(accR[j], rr, rd);
            unpack2(accI[j], ii, id_);
            float Pr = gw2 * (rr * rr + ii * ii);
            g_pr[t * F + f]   = Pr;
            lmax = fmaxf(lmax, Pr);
            g_pdel[t * F + f] = gw2 * (rd * rd + id_ * id_);
        }
    }
#pragma unroll
    for (int o = 16; o > 0; o >>= 1)
        lmax = fmaxf(lmax, __shfl_xor_sync(0xFFFFFFFFu, lmax, o));
    if ((tid & 31) == 0) wmax[tid >> 5] = lmax;
    __syncthreads();
    if (tid == 0) {
        float m = fmaxf(fmaxf(wmax[0], wmax[1]), fmaxf(wmax[2], wmax[3]));
        atomicMax(&g_ctl.pmaxi, __float_as_uint(m));
    }
}

// ---------------------------------------------------------------------------
// Threshold + fused loss + last-block finalize. One frame per CTA.
// ---------------------------------------------------------------------------
__global__ void __launch_bounds__(128) thresh_kernel(float* out, int T, int N) {
    __shared__ float  sb[F], pw[F];
    __shared__ float  mcv[128];
    __shared__ short  order[128], obk[128];
    __shared__ unsigned char keepf[128], mark[258];
    __shared__ float4 msk[128];             // (mz, mb2, ms2, pad)
    __shared__ float2 um[129];              // (mantissa, exp2) of suffix sums
    __shared__ short  cum[F];
    __shared__ int    cnt[8], cbase[8];
    __shared__ int    nsh, Ksh;
    __shared__ float  red[4];

    const float LG  = 0.33219280948873623f;   // 0.1*log2(10)
    const float SLP = 27.f * LG;
    const float DB2 = 3.0102999566398120f;    // 10/log2(10)

    int tid = threadIdx.x;
    int w = tid >> 5, l = tid & 31;
    int t = blockIdx.x;

    // SC = 10^9.6 / Pmax  (== 10^((96-pm)/10))
    float Pmax = fmaxf(__uint_as_float(g_ctl.pmaxi), 1e-20f);
    float SC = ex2(31.890509711463527f - lg2(Pmax));

    const float* prp = g_pr + t * F;
    for (int f = tid; f < F; f += 128) {
        sb[f] = g_bark[f];
        pw[f] = SC * fmaxf(prp[f], 1e-20f);
    }
    keepf[tid] = 1;
    mark[tid] = 0; mark[tid + 128] = 0;
    if (tid == 0) { mark[256] = 0; }
    __syncthreads();

    // local-max + ATH candidates: f=tid (chunk w), f=tid+128 (chunk 4+w)
    float p3A = 0.f, p3B = 0.f;
    bool  vA = false, vB = false;
    if (tid >= 1) {
        float a = pw[tid - 1], b = pw[tid], c = pw[tid + 1];
        p3A = a + b + c;
        vA = (b > a) && (b > c) && (p3A > g_athpow[tid]);
    }
    {
        int f = tid + 128;   // 128..255
        float a = pw[f - 1], b = pw[f], c = pw[f + 1];
        p3B = a + b + c;
        vB = (b > a) && (b > c) && (p3B > g_athpow[f]);
    }
    unsigned mA = __ballot_sync(0xFFFFFFFFu, vA);
    unsigned mB = __ballot_sync(0xFFFFFFFFu, vB);
    if (l == 0) { cnt[w] = __popc(mA); cnt[4 + w] = __popc(mB); }
    __syncthreads();
    if (tid == 0) {
        int s = 0;
        for (int c = 0; c < 8; c++) { cbase[c] = s; s += cnt[c]; }
        nsh = s;
    }
    __syncthreads();
    unsigned below = (1u << l) - 1u;
    if (vA) {
        int pos = cbase[w] + __popc(mA & below);
        order[pos] = (short)tid;
        mcv[pos]   = DB2 * lg2(p3A);
    }
    if (vB) {
        int pos = cbase[4 + w] + __popc(mB & below);
        order[pos] = (short)(tid + 128);
        mcv[pos]   = DB2 * lg2(p3B);
    }
    __syncthreads();

    // faithful sequential dedup (bark indexed by LIST POSITION, as in ref)
    if (tid == 0) {
        int n = nsh, ip = 0;
        for (int i = 1; i < n; i++) {
            if (sb[i] - sb[ip] < 0.5f) {
                if (mcv[ip] < mcv[i]) { keepf[ip] = 0; ip++; }
                else                    keepf[i]  = 0;
            } else ip = i;
        }
    }
    __syncthreads();

    // warp 0: compact kept maskers, mark bins, parallel suffix sums (double)
    if (tid < 32) {
        int n = nsh, basep = 0;
        for (int c0 = 0; c0 < n; c0 += 32) {
            int i = c0 + tid;
            bool ok = (i < n) && keepf[i];
            unsigned m = __ballot_sync(0xFFFFFFFFu, ok);
            if (ok) {
                int pos = basep + __popc(m & ((1u << tid) - 1u));
                int o = order[i];
                float mv = mcv[i];
                obk[pos] = (short)o;
                mark[o]  = 1;
                msk[pos] = make_float4(sb[o], (mv + g_dshift[o]) * LG,
                                       fmaf(0.37f, fmaxf(mv - 40.f, 0.f), -27.f) * LG,
                                       0.f);
            }
            basep += __popc(m);
        }
        int K = basep;
        if (tid == 0) Ksh = K;
        // suffix sums of 2^(mb2 - SLP*mz) in double, high chunk first
        double carry = 0.0;
        if (K > 0) {
            for (int c0 = ((K - 1) >> 5) << 5; c0 >= 0; c0 -= 32) {
                int idx = c0 + tid;
                double p = 0.0;
                if (idx < K) {
                    float4 m4 = msk[idx];
                    float e = fmaf(-SLP, m4.x, m4.y);
                    float ei = floorf(e);
                    p = scalbn((double)ex2(e - ei), (int)ei);
                }
#pragma unroll
                for (int o = 1; o < 32; o <<= 1) {
                    double v = __shfl_down_sync(0xFFFFFFFFu, p, o);
                    if (tid + o < 32) p += v;
                }
                p += carry;
                if (idx < K) {
                    int ex; double mant = frexp(p, &ex);
                    um[idx] = make_float2((float)mant, (float)ex);
                }
                carry = __shfl_sync(0xFFFFFFFFu, p, 0);
            }
        }
        if (tid == 0) um[K] = make_float2(0.f, -1e30f);
    }
    __syncthreads();

    // exclusive prefix count of masker bins -> cum[f] = #maskers with bin < f
    {
        int v0 = mark[2 * tid], v1 = mark[2 * tid + 1];
        int s2 = v0 + v1;
        int incl = s2;
#pragma unroll
        for (int o = 1; o < 32; o <<= 1) {
            int u = __shfl_up_sync(0xFFFFFFFFu, incl, o);
            if (l >= o) incl += u;
        }
        if (l == 31) cnt[w] = incl;
        __syncthreads();
        if (tid == 0) {
            int b = 0;
            for (int c = 0; c < 4; c++) { cbase[c] = b; b += cnt[c]; }
        }
        __syncthreads();
        int excl = cbase[w] + incl - s2;
        cum[2 * tid]     = (short)excl;
        cum[2 * tid + 1] = (short)(excl + v0);
        if (tid == 0) cum[256] = (short)Ksh;
    }
    __syncthreads();

    const float* pdp = g_pdel + t * F;
    float lsum = 0.f;
    for (int f = tid; f < F; f += 128) {
        float bf = sb[f];
        int j0 = cum[f];
        float sum = g_athpow[f];
        for (int kk = 0; kk < j0; kk++) {
            float4 m4 = msk[kk];
            sum += ex2(fmaf(m4.z, bf - m4.x, m4.y));
        }
        float2 u = um[j0];
        sum += u.x * ex2(fmaf(SLP, bf, u.y));
        float v = fmaf(SC, pdp[f], -sum);
        if (v > 0.f) lsum += v;
    }
#pragma unroll
    for (int o = 16; o > 0; o >>= 1)
        lsum += __shfl_xor_sync(0xFFFFFFFFu, lsum, o);
    if (l == 0) red[w] = lsum;
    __syncthreads();
    if (tid == 0) {
        atomicAdd(&g_ctl.acc, (double)(red[0] + red[1] + red[2] + red[3]));
        __threadfence();
        unsigned d = atomicAdd(&g_ctl.done, 1u);
        if (d == (unsigned)(gridDim.x - 1)) {
            double acc = g_ctl.acc;
            out[0] = (float)(1e-6 * acc / (double)N);
        }
    }
}

// ---------------------------------------------------------------------------
extern "C" void kernel_launch(void* const* d_in, const int* in_sizes, int n_in,
                              void* d_out, int out_size)
{
    const float* xadv = (const float*)d_in[0];
    const float* xref = (const float*)d_in[1];
    float* out = (float*)d_out;

    int L = in_sizes[0];
    int T = (L - W) / HOP + 1;
    if (T > MAXT) T = MAXT;
    int N  = T * F;
    int Lv = (T - 1) * HOP + W;
    int ng = (T + FT - 1) / FT;

    void* ctl_addr = nullptr;
    cudaGetSymbolAddress(&ctl_addr, g_ctl);
    cudaMemsetAsync(ctl_addr, 0, sizeof(Ctl));

    stft_kernel<<<dim3(ng, 3), 128>>>(xadv, xref, T, Lv);
    thresh_kernel<<<T, 128>>>(out, T, N);
}

// round 10
// speedup vs baseline: 1.0020x; 1.0020x over previous
#include <cuda_runtime.h>
#include <math.h>

#define W 512
#define F 257
#define HOP 128
#define FT 4
#define MAXT 1300
#define SPAN (W + (FT - 1) * HOP)   // 896

typedef unsigned long long ull;

__device__ __forceinline__ float ex2(float x) {
    float r; asm("ex2.approx.ftz.f32 %0, %1;" : "=f"(r) : "f"(x)); return r;
}
__device__ __forceinline__ float lg2(float x) {
    float r; asm("lg2.approx.ftz.f32 %0, %1;" : "=f"(r) : "f"(x)); return r;
}
__device__ __forceinline__ ull pack2(float lo, float hi) {
    ull r; asm("mov.b64 %0, {%1, %2};" : "=l"(r) : "f"(lo), "f"(hi)); return r;
}
__device__ __forceinline__ void unpack2(ull v, float &lo, float &hi) {
    asm("mov.b64 {%0, %1}, %2;" : "=f"(lo), "=f"(hi) : "l"(v));
}
__device__ __forceinline__ void ffma2(ull &acc, ull a, ull b) {
    asm("fma.rn.f32x2 %0, %1, %2, %0;" : "+l"(acc) : "l"(a), "l"(b));
}

// ---- static device scratch ----
struct Ctl { unsigned int pmax[64]; unsigned int done; };
__device__ Ctl   g_ctl;
__device__ float g_lpart[MAXT];
__device__ float g_bark[F], g_dshift[F], g_athpow[F];
__device__ float g_pr  [MAXT * F];
__device__ float g_pdel[MAXT * F];

// ---------------------------------------------------------------------------
// Mega STFT kernel. blockIdx.y: 0/1 = DFT parity CTAs, 2 = bin256 + tables.
// ---------------------------------------------------------------------------
__global__ void __launch_bounds__(128) stft_kernel(
    const float* __restrict__ xadv, const float* __restrict__ xref,
    int T, int Lv)
{
    int tid = threadIdx.x;
    int par = blockIdx.y;
    int t0  = blockIdx.x * FT;

    if (par == 2) {
        // ---- bin 256 (one warp per frame) + constant tables (CTA x==0) ----
        int wid = tid >> 5, l = tid & 31;
        int t = t0 + wid;
        float Pr = 0.f;
        if (t < T) {
            int base = t * HOP;
            float rr = 0.f, rd = 0.f;
            for (int n = l; n < 512; n += 32) {
                float hw = 0.5f - 0.5f * cospif((float)n * (1.f / 256.f));
                if (n & 1) hw = -hw;
                float r = xref[base + n], a = xadv[base + n];
                rr = fmaf(hw, r, rr);
                rd = fmaf(hw, a - r, rd);
            }
#pragma unroll
            for (int o = 16; o > 0; o >>= 1) {
                rr += __shfl_xor_sync(0xFFFFFFFFu, rr, o);
                rd += __shfl_xor_sync(0xFFFFFFFFu, rd, o);
            }
            const float gw2 = 1.0172526041666667e-5f;
            Pr = gw2 * rr * rr;
            if (l == 0) {
                g_pr[t * F + 256]   = Pr;
                g_pdel[t * F + 256] = gw2 * rd * rd;
                atomicMax(&g_ctl.pmax[(blockIdx.x + wid) & 63], __float_as_uint(Pr));
            }
        }
        if (blockIdx.x == 0) {
            for (int i = tid; i < F; i += 128) {
                double freq = (double)i * (8000.0 / 256.0);
                double bark = 13.0 * atan(0.00076 * freq)
                            + 3.5  * atan((freq / 7500.0) * (freq / 7500.0));
                float bf = (float)bark;
                g_bark[i]   = bf;
                g_dshift[i] = -6.025f - 0.275f * bf;
                if (freq >= 20.0 && freq <= 20000.0) {
                    double fk = freq * 0.001;
                    double ath = 3.64 * pow(fk, -0.8)
                               - 6.5  * exp(-0.6 * (fk - 3.3) * (fk - 3.3))
                               + 0.001 * fk * fk * fk * fk
                               - 12.0;
                    g_athpow[i] = exp10f((float)ath * 0.1f);
                } else {
                    g_athpow[i] = 0.0f;
                }
            }
        }
        return;
    }

    // ---- folded real DFT ----
    __shared__ float      xr[SPAN], xd[SPAN];
    __shared__ ulonglong2 eo[FT][128];      // (e_ref,e_del) , (o_ref,o_del)
    __shared__ float      edge[FT][6];
    __shared__ ulonglong2 tw[544];          // ((c,c),(s,s)); idx k+(k>>4)
    __shared__ float      wmax[4];

    int base = t0 * HOP;

    for (int k = tid; k < 512; k += 128) {
        float s, c;
        sincospif((float)k * (1.f / 256.f), &s, &c);
        int pk = k + (k >> 4);
        ulonglong2 u; u.x = pack2(c, c); u.y = pack2(s, s);
        tw[pk] = u;
    }
    for (int i = tid; i < SPAN; i += 128) {
        int g = base + i;
        float r = 0.f, d = 0.f;
        if (g < Lv) { r = xref[g]; d = xadv[g] - r; }
        xr[i] = r; xd[i] = d;
    }
    __syncthreads();

    float s = par ? -1.f : 1.f;
    for (int idx = tid; idx < FT * 128; idx += 128) {
        int j = idx >> 7, n = idx & 127;
        const float* fr = xr + j * HOP;
        const float* fd = xd + j * HOP;
        if (n == 0) {
            edge[j][0] = fr[256];
            edge[j][1] = (fr[128] + fr[384]) * 0.5f;
            edge[j][2] = (fr[128] - fr[384]) * 0.5f;
            edge[j][3] = fd[256];
            edge[j][4] = (fd[128] + fd[384]) * 0.5f;
            edge[j][5] = (fd[128] - fd[384]) * 0.5f;
        } else {
            float h1 = 0.5f - 0.5f * cospif((float)n * (1.f / 256.f));
            float h2 = 0.5f - 0.5f * cospif((float)(256 - n) * (1.f / 256.f));
            float a1 = fr[n], a2 = fr[512 - n], a3 = fr[256 - n], a4 = fr[256 + n];
            float b1 = fd[n], b2 = fd[512 - n], b3 = fd[256 - n], b4 = fd[256 + n];
            float er = (a1 + a2) * h1 + s * ((a3 + a4) * h2);
            float orf = (a1 - a2) * h1 - s * ((a3 - a4) * h2);
            float ed = (b1 + b2) * h1 + s * ((b3 + b4) * h2);
            float od = (b1 - b2) * h1 - s * ((b3 - b4) * h2);
            ulonglong2 u;
            u.x = pack2(er, ed);
            u.y = pack2(orf, od);
            eo[j][n] = u;
        }
    }
    __syncthreads();

    int f = 2 * tid + par;
    float sgn = (tid & 1) ? -1.f : 1.f;
    ull accR[FT], accI[FT];
#pragma unroll
    for (int j = 0; j < FT; j++) {
        if (par == 0) {
            accR[j] = pack2(fmaf(sgn, edge[j][1], edge[j][0]),
                            fmaf(sgn, edge[j][4], edge[j][3]));
            accI[j] = pack2(0.f, 0.f);
        } else {
            accR[j] = pack2(-edge[j][0], -edge[j][3]);
            accI[j] = pack2(sgn * edge[j][2], sgn * edge[j][5]);
        }
    }
    int k = f;
#pragma unroll 4
    for (int n = 1; n < 128; n++) {
        ulonglong2 cs = tw[k + (k >> 4)];
#pragma unroll
        for (int j = 0; j < FT; j++) {
            ulonglong2 v = eo[j][n];
            ffma2(accR[j], v.x, cs.x);
            ffma2(accI[j], v.y, cs.y);
        }
        k = (k + f) & 511;
    }
    const float gw2 = 1.0172526041666667e-5f;   // (8/3)/512^2
    float lmax = 0.f;
#pragma unroll
    for (int j = 0; j < FT; j++) {
        int t = t0 + j;
        if (t < T) {
            float rr, rd, ii, id_;
            unpack2(accR[j], rr, rd);
            unpack2(accI[j], ii, id_);
            float Pr = gw2 * (rr * rr + ii * ii);
            g_pr[t * F + f]   = Pr;
            lmax = fmaxf(lmax, Pr);
            g_pdel[t * F + f] = gw2 * (rd * rd + id_ * id_);
        }
    }
#pragma unroll
    for (int o = 16; o > 0; o >>= 1)
        lmax = fmaxf(lmax, __shfl_xor_sync(0xFFFFFFFFu, lmax, o));
    if ((tid & 31) == 0) wmax[tid >> 5] = lmax;
    __syncthreads();
    if (tid == 0) {
        float m = fmaxf(fmaxf(wmax[0], wmax[1]), fmaxf(wmax[2], wmax[3]));
        atomicMax(&g_ctl.pmax[blockIdx.x & 63], __float_as_uint(m));
    }
}

// ---------------------------------------------------------------------------
// Threshold + fused loss + last-block finalize. One frame per CTA.
// ---------------------------------------------------------------------------
__global__ void __launch_bounds__(128) thresh_kernel(float* out, int T, int N) {
    __shared__ float  sb[F], pw[F];
    __shared__ float  mcv[128];
    __shared__ short  order[128], obk[128];
    __shared__ unsigned char keepf[128], mark[258];
    __shared__ float4 msk[128];             // (mz, mb2, ms2, pad)
    __shared__ float2 um[129];              // (mantissa, exp2) of suffix sums
    __shared__ short  cum[F];
    __shared__ int    cnt[8], cbase[8];
    __shared__ int    nsh, Ksh, slast;
    __shared__ float  red[4];
    __shared__ double dred[4];

    const float LG  = 0.33219280948873623f;   // 0.1*log2(10)
    const float SLP = 27.f * LG;
    const float DB2 = 3.0102999566398120f;    // 10/log2(10)

    int tid = threadIdx.x;
    int w = tid >> 5, l = tid & 31;
    int t = blockIdx.x;

    // reduce the 64 spread pmax slots
    {
        float pv = (tid < 64) ? __uint_as_float(g_ctl.pmax[tid]) : 0.f;
#pragma unroll
        for (int o = 16; o > 0; o >>= 1)
            pv = fmaxf(pv, __shfl_xor_sync(0xFFFFFFFFu, pv, o));
        if (l == 0) red[w] = pv;
    }
    __syncthreads();
    float Pmax = fmaxf(fmaxf(red[0], red[1]), 1e-20f);
    // SC = 10^9.6 / Pmax  (== 10^((96-pm)/10))
    float SC = ex2(31.890509711463527f - lg2(Pmax));

    const float* prp = g_pr + t * F;
    for (int f = tid; f < F; f += 128) {
        sb[f] = g_bark[f];
        pw[f] = SC * fmaxf(prp[f], 1e-20f);
    }
    keepf[tid] = 1;
    mark[tid] = 0; mark[tid + 128] = 0;
    if (tid == 0) { mark[256] = 0; }
    __syncthreads();

    // local-max + ATH candidates: f=tid (chunk w), f=tid+128 (chunk 4+w)
    float p3A = 0.f, p3B = 0.f;
    bool  vA = false, vB = false;
    if (tid >= 1) {
        float a = pw[tid - 1], b = pw[tid], c = pw[tid + 1];
        p3A = a + b + c;
        vA = (b > a) && (b > c) && (p3A > g_athpow[tid]);
    }
    {
        int f = tid + 128;   // 128..255
        float a = pw[f - 1], b = pw[f], c = pw[f + 1];
        p3B = a + b + c;
        vB = (b > a) && (b > c) && (p3B > g_athpow[f]);
    }
    unsigned mA = __ballot_sync(0xFFFFFFFFu, vA);
    unsigned mB = __ballot_sync(0xFFFFFFFFu, vB);
    if (l == 0) { cnt[w] = __popc(mA); cnt[4 + w] = __popc(mB); }
    __syncthreads();
    if (tid == 0) {
        int s = 0;
        for (int c = 0; c < 8; c++) { cbase[c] = s; s += cnt[c]; }
        nsh = s;
    }
    __syncthreads();
    unsigned below = (1u << l) - 1u;
    if (vA) {
        int pos = cbase[w] + __popc(mA & below);
        order[pos] = (short)tid;
        mcv[pos]   = DB2 * lg2(p3A);
    }
    if (vB) {
        int pos = cbase[4 + w] + __popc(mB & below);
        order[pos] = (short)(tid + 128);
        mcv[pos]   = DB2 * lg2(p3B);
    }
    __syncthreads();

    // faithful sequential dedup (bark indexed by LIST POSITION, as in ref)
    if (tid == 0) {
        int n = nsh, ip = 0;
        for (int i = 1; i < n; i++) {
            if (sb[i] - sb[ip] < 0.5f) {
                if (mcv[ip] < mcv[i]) { keepf[ip] = 0; ip++; }
                else                    keepf[i]  = 0;
            } else ip = i;
        }
    }
    __syncthreads();

    // warp 0: compact kept maskers, mark bins, parallel suffix sums (double)
    if (tid < 32) {
        int n = nsh, basep = 0;
        for (int c0 = 0; c0 < n; c0 += 32) {
            int i = c0 + tid;
            bool ok = (i < n) && keepf[i];
            unsigned m = __ballot_sync(0xFFFFFFFFu, ok);
            if (ok) {
                int pos = basep + __popc(m & ((1u << tid) - 1u));
                int o = order[i];
                float mv = mcv[i];
                obk[pos] = (short)o;
                mark[o]  = 1;
                msk[pos] = make_float4(sb[o], (mv + g_dshift[o]) * LG,
                                       fmaf(0.37f, fmaxf(mv - 40.f, 0.f), -27.f) * LG,
                                       0.f);
            }
            basep += __popc(m);
        }
        int K = basep;
        if (tid == 0) Ksh = K;
        // suffix sums of 2^(mb2 - SLP*mz) in double, high chunk first
        double carry = 0.0;
        if (K > 0) {
            for (int c0 = ((K - 1) >> 5) << 5; c0 >= 0; c0 -= 32) {
                int idx = c0 + tid;
                double p = 0.0;
                if (idx < K) {
                    float4 m4 = msk[idx];
                    float e = fmaf(-SLP, m4.x, m4.y);
                    float ei = floorf(e);
                    p = scalbn((double)ex2(e - ei), (int)ei);
                }
#pragma unroll
                for (int o = 1; o < 32; o <<= 1) {
                    double v = __shfl_down_sync(0xFFFFFFFFu, p, o);
                    if (tid + o < 32) p += v;
                }
                p += carry;
                if (idx < K) {
                    int ex; double mant = frexp(p, &ex);
                    um[idx] = make_float2((float)mant, (float)ex);
                }
                carry = __shfl_sync(0xFFFFFFFFu, p, 0);
            }
        }
        if (tid == 0) um[K] = make_float2(0.f, -1e30f);
    }
    __syncthreads();

    // exclusive prefix count of masker bins -> cum[f] = #maskers with bin < f
    {
        int v0 = mark[2 * tid], v1 = mark[2 * tid + 1];
        int s2 = v0 + v1;
        int incl = s2;
#pragma unroll
        for (int o = 1; o < 32; o <<= 1) {
            int u = __shfl_up_sync(0xFFFFFFFFu, incl, o);
            if (l >= o) incl += u;
        }
        if (l == 31) cnt[w] = incl;
        __syncthreads();
        if (tid == 0) {
            int b = 0;
            for (int c = 0; c < 4; c++) { cbase[c] = b; b += cnt[c]; }
        }
        __syncthreads();
        int excl = cbase[w] + incl - s2;
        cum[2 * tid]     = (short)excl;
        cum[2 * tid + 1] = (short)(excl + v0);
        if (tid == 0) cum[256] = (short)Ksh;
    }
    __syncthreads();

    const float* pdp = g_pdel + t * F;
    float lsum = 0.f;
    for (int f = tid; f < F; f += 128) {
        float bf = sb[f];
        int j0 = cum[f];
        float sum = g_athpow[f];
        for (int kk = 0; kk < j0; kk++) {
            float4 m4 = msk[kk];
            sum += ex2(fmaf(m4.z, bf - m4.x, m4.y));
        }
        float2 u = um[j0];
        sum += u.x * ex2(fmaf(SLP, bf, u.y));
        float v = fmaf(SC, pdp[f], -sum);
        if (v > 0.f) lsum += v;
    }
#pragma unroll
    for (int o = 16; o > 0; o >>= 1)
        lsum += __shfl_xor_sync(0xFFFFFFFFu, lsum, o);
    if (l == 0) red[w] = lsum;
    __syncthreads();
    if (tid == 0) {
        g_lpart[t] = red[0] + red[1] + red[2] + red[3];
        __threadfence();
        unsigned d = atomicAdd(&g_ctl.done, 1u);
        slast = (d == (unsigned)(gridDim.x - 1)) ? 1 : 0;
    }
    __syncthreads();
    if (slast) {
        __threadfence();
        double local = 0.0;
        for (int i = tid; i < T; i += 128) local += (double)g_lpart[i];
#pragma unroll
        for (int o = 16; o > 0; o >>= 1)
            local += __shfl_xor_sync(0xFFFFFFFFu, local, o);
        if (l == 0) dred[w] = local;
        __syncthreads();
        if (tid == 0) {
            double acc = dred[0] + dred[1] + dred[2] + dred[3];
            out[0] = (float)(1e-6 * acc / (double)N);
        }
    }
}

// ---------------------------------------------------------------------------
extern "C" void kernel_launch(void* const* d_in, const int* in_sizes, int n_in,
                              void* d_out, int out_size)
{
    const float* xadv = (const float*)d_in[0];
    const float* xref = (const float*)d_in[1];
    float* out = (float*)d_out;

    int L = in_sizes[0];
    int T = (L - W) / HOP + 1;
    if (T > MAXT) T = MAXT;
    int N  = T * F;
    int Lv = (T - 1) * HOP + W;
    int ng = (T + FT - 1) / FT;

    void* ctl_addr = nullptr;
    cudaGetSymbolAddress(&ctl_addr, g_ctl);
    cudaMemsetAsync(ctl_addr, 0, sizeof(Ctl));

    stft_kernel<<<dim3(ng, 3), 128>>>(xadv, xref, T, Lv);
    thresh_kernel<<<T, 128>>>(out, T, N);
}

// round 12
// speedup vs baseline: 1.0425x; 1.0404x over previous
#include <cuda_runtime.h>
#include <math.h>

#define W 512
#define F 257
#define HOP 128
#define FT 8
#define MAXT 1300
#define SPAN (W + (FT - 1) * HOP)   // 1408

typedef unsigned long long ull;

__device__ __forceinline__ float ex2(float x) {
    float r; asm("ex2.approx.ftz.f32 %0, %1;" : "=f"(r) : "f"(x)); return r;
}
__device__ __forceinline__ float lg2(float x) {
    float r; asm("lg2.approx.ftz.f32 %0, %1;" : "=f"(r) : "f"(x)); return r;
}
__device__ __forceinline__ ull pack2(float lo, float hi) {
    ull r; asm("mov.b64 %0, {%1, %2};" : "=l"(r) : "f"(lo), "f"(hi)); return r;
}
__device__ __forceinline__ void unpack2(ull v, float &lo, float &hi) {
    asm("mov.b64 {%0, %1}, %2;" : "=f"(lo), "=f"(hi) : "l"(v));
}
__device__ __forceinline__ void ffma2(ull &acc, ull a, ull b) {
    asm("fma.rn.f32x2 %0, %1, %2, %0;" : "+l"(acc) : "l"(a), "l"(b));
}

// ---- static device scratch (zero-initialized; self-resetting each run) ----
struct Ctl { unsigned int pmax[64]; unsigned int done; };
__device__ Ctl   g_ctl;
__device__ float g_lpart[MAXT];
__device__ float g_bark[F], g_dshift[F], g_athpow[F];
__device__ short g_lim[F], g_bstart[F];
__device__ float g_pr  [MAXT * F];
__device__ float g_pdel[MAXT * F];

// ---------------------------------------------------------------------------
// Mega STFT kernel. blockIdx.y: 0/1 = DFT parity CTAs, 2 = bin256 + tables.
// ---------------------------------------------------------------------------
__global__ void __launch_bounds__(128) stft_kernel(
    const float* __restrict__ xadv, const float* __restrict__ xref,
    int T, int Lv)
{
    int tid = threadIdx.x;
    int par = blockIdx.y;
    int t0  = blockIdx.x * FT;

    if (par == 2) {
        // ---- bin 256: FT frames per CTA, 4 warps x 2 reps ----
        int wid = tid >> 5, l = tid & 31;
#pragma unroll
        for (int rep = 0; rep < 2; rep++) {
            int t = t0 + wid + rep * 4;
            if (t < T) {
                int base = t * HOP;
                float rr = 0.f, rd = 0.f;
                for (int n = l; n < 512; n += 32) {
                    float hw = 0.5f - 0.5f * cospif((float)n * (1.f / 256.f));
                    if (n & 1) hw = -hw;
                    float r = xref[base + n], a = xadv[base + n];
                    rr = fmaf(hw, r, rr);
                    rd = fmaf(hw, a - r, rd);
                }
#pragma unroll
                for (int o = 16; o > 0; o >>= 1) {
                    rr += __shfl_xor_sync(0xFFFFFFFFu, rr, o);
                    rd += __shfl_xor_sync(0xFFFFFFFFu, rd, o);
                }
                const float gw2 = 1.0172526041666667e-5f;
                float Pr = gw2 * rr * rr;
                if (l == 0) {
                    g_pr[t * F + 256]   = Pr;
                    g_pdel[t * F + 256] = gw2 * rd * rd;
                    atomicMax(&g_ctl.pmax[(blockIdx.x * 8 + wid + rep * 4) & 63],
                              __float_as_uint(Pr));
                }
            }
        }
        if (blockIdx.x == 0) {
            __shared__ float bsm[F];
            for (int i = tid; i < F; i += 128) {
                double freq = (double)i * (8000.0 / 256.0);
                double bark = 13.0 * atan(0.00076 * freq)
                            + 3.5  * atan((freq / 7500.0) * (freq / 7500.0));
                float bf = (float)bark;
                bsm[i]      = bf;
                g_bark[i]   = bf;
                g_dshift[i] = -6.025f - 0.275f * bf;
                if (freq >= 20.0 && freq <= 20000.0) {
                    double fk = freq * 0.001;
                    double ath = 3.64 * pow(fk, -0.8)
                               - 6.5  * exp(-0.6 * (fk - 3.3) * (fk - 3.3))
                               + 0.001 * fk * fk * fk * fk
                               - 12.0;
                    g_athpow[i] = exp10f((float)ath * 0.1f);
                } else {
                    g_athpow[i] = 0.0f;
                }
            }
            __syncthreads();
            for (int i = tid; i < F; i += 128) {
                // lim[i] = max q with bark[q] < bark[i] + 0.5
                int q = i;
                float hi = bsm[i] + 0.5f;
                while (q + 1 < F && bsm[q + 1] < hi) q++;
                g_lim[i] = (short)q;
                // bstart[i] = first idx with bark >= bark[i] - 8
                float lo = bsm[i] - 8.f;
                int l0 = 0, h0 = i;
                while (l0 < h0) {
                    int m = (l0 + h0) >> 1;
                    if (bsm[m] < lo) l0 = m + 1; else h0 = m;
                }
                g_bstart[i] = (short)l0;
            }
        }
        return;
    }

    // ---- folded real DFT, FT frames ----
    __shared__ float      xr[SPAN], xd[SPAN];
    __shared__ ulonglong2 eo[FT][128];      // (e_ref,e_del) , (o_ref,o_del)
    __shared__ float      edge[FT][6];
    __shared__ ulonglong2 tw[544];          // ((c,c),(s,s)); idx k+(k>>4)
    __shared__ float      wmax[4];

    int base = t0 * HOP;

    for (int k = tid; k < 512; k += 128) {
        float s, c;
        sincospif((float)k * (1.f / 256.f), &s, &c);
        int pk = k + (k >> 4);
        ulonglong2 u; u.x = pack2(c, c); u.y = pack2(s, s);
        tw[pk] = u;
    }
    for (int i = tid; i < SPAN; i += 128) {
        int g = base + i;
        float r = 0.f, d = 0.f;
        if (g < Lv) { r = xref[g]; d = xadv[g] - r; }
        xr[i] = r; xd[i] = d;
    }
    __syncthreads();

    float s = par ? -1.f : 1.f;
    for (int idx = tid; idx < FT * 128; idx += 128) {
        int j = idx >> 7, n = idx & 127;
        const float* fr = xr + j * HOP;
        const float* fd = xd + j * HOP;
        if (n == 0) {
            edge[j][0] = fr[256];
            edge[j][1] = (fr[128] + fr[384]) * 0.5f;
            edge[j][2] = (fr[128] - fr[384]) * 0.5f;
            edge[j][3] = fd[256];
            edge[j][4] = (fd[128] + fd[384]) * 0.5f;
            edge[j][5] = (fd[128] - fd[384]) * 0.5f;
        } else {
            float h1 = 0.5f - 0.5f * cospif((float)n * (1.f / 256.f));
            float h2 = 0.5f - 0.5f * cospif((float)(256 - n) * (1.f / 256.f));
            float a1 = fr[n], a2 = fr[512 - n], a3 = fr[256 - n], a4 = fr[256 + n];
            float b1 = fd[n], b2 = fd[512 - n], b3 = fd[256 - n], b4 = fd[256 + n];
            float er = (a1 + a2) * h1 + s * ((a3 + a4) * h2);
            float orf = (a1 - a2) * h1 - s * ((a3 - a4) * h2);
            float ed = (b1 + b2) * h1 + s * ((b3 + b4) * h2);
            float od = (b1 - b2) * h1 - s * ((b3 - b4) * h2);
            ulonglong2 u;
            u.x = pack2(er, ed);
            u.y = pack2(orf, od);
            eo[j][n] = u;
        }
    }
    __syncthreads();

    int f = 2 * tid + par;
    float sgn = (tid & 1) ? -1.f : 1.f;
    ull accR[FT], accI[FT];
#pragma unroll
    for (int j = 0; j < FT; j++) {
        if (par == 0) {
            accR[j] = pack2(fmaf(sgn, edge[j][1], edge[j][0]),
                            fmaf(sgn, edge[j][4], edge[j][3]));
            accI[j] = pack2(0.f, 0.f);
        } else {
            accR[j] = pack2(-edge[j][0], -edge[j][3]);
            accI[j] = pack2(sgn * edge[j][2], sgn * edge[j][5]);
        }
    }
    int k = f;
#pragma unroll 2
    for (int n = 1; n < 128; n++) {
        ulonglong2 cs = tw[k + (k >> 4)];
#pragma unroll
        for (int j = 0; j < FT; j++) {
            ulonglong2 v = eo[j][n];
            ffma2(accR[j], v.x, cs.x);
            ffma2(accI[j], v.y, cs.y);
        }
        k = (k + f) & 511;
    }
    const float gw2 = 1.0172526041666667e-5f;   // (8/3)/512^2
    float lmax = 0.f;
#pragma unroll
    for (int j = 0; j < FT; j++) {
        int t = t0 + j;
        if (t < T) {
            float rr, rd, ii, id_;
            unpack2(accR[j], rr, rd);
            unpack2(accI[j], ii, id_);
            float Pr = gw2 * (rr * rr + ii * ii);
            g_pr[t * F + f]   = Pr;
            lmax = fmaxf(lmax, Pr);
            g_pdel[t * F + f] = gw2 * (rd * rd + id_ * id_);
        }
    }
#pragma unroll
    for (int o = 16; o > 0; o >>= 1)
        lmax = fmaxf(lmax, __shfl_xor_sync(0xFFFFFFFFu, lmax, o));
    if ((tid & 31) == 0) wmax[tid >> 5] = lmax;
    __syncthreads();
    if (tid == 0) {
        float m = fmaxf(fmaxf(wmax[0], wmax[1]), fmaxf(wmax[2], wmax[3]));
        atomicMax(&g_ctl.pmax[blockIdx.x & 63], __float_as_uint(m));
    }
}

// ---------------------------------------------------------------------------
// Threshold + fused loss + last-block finalize + state self-reset.
// ---------------------------------------------------------------------------
__global__ void __launch_bounds__(128) thresh_kernel(float* out, int T, int N) {
    __shared__ float  sb[F], pw[F];
    __shared__ float  mcv[128];
    __shared__ short  order[128], slim[F];
    __shared__ unsigned char keepf[128], mark[258];
    __shared__ float4 msk[128];             // (mz, mb2, ms2, pad)
    __shared__ float2 um[129];              // (mantissa, exp2) of suffix sums
    __shared__ short  cum[F];
    __shared__ int    cnt[8], cbase[8];
    __shared__ int    nsh, Ksh, slast;
    __shared__ float  red[4];
    __shared__ double dred[4];

    const float LG  = 0.33219280948873623f;   // 0.1*log2(10)
    const float SLP = 27.f * LG;
    const float DB2 = 3.0102999566398120f;    // 10/log2(10)

    int tid = threadIdx.x;
    int w = tid >> 5, l = tid & 31;
    int t = blockIdx.x;

    // reduce the 64 spread pmax slots
    {
        float pv = (tid < 64) ? __uint_as_float(g_ctl.pmax[tid]) : 0.f;
#pragma unroll
        for (int o = 16; o > 0; o >>= 1)
            pv = fmaxf(pv, __shfl_xor_sync(0xFFFFFFFFu, pv, o));
        if (l == 0) red[w] = pv;
    }
    __syncthreads();
    float Pmax = fmaxf(fmaxf(red[0], red[1]), 1e-20f);
    // SC = 10^9.6 / Pmax  (== 10^((96-pm)/10))
    float SC = ex2(31.890509711463527f - lg2(Pmax));

    const float* prp = g_pr + t * F;
    for (int f = tid; f < F; f += 128) {
        sb[f]   = g_bark[f];
        slim[f] = g_lim[f];
        pw[f]   = SC * fmaxf(prp[f], 1e-20f);
    }
    keepf[tid] = 1;
    mark[tid] = 0; mark[tid + 128] = 0;
    if (tid == 0) { mark[256] = 0; }
    __syncthreads();

    // local-max + ATH candidates: f=tid (chunk w), f=tid+128 (chunk 4+w)
    float p3A = 0.f, p3B = 0.f;
    bool  vA = false, vB = false;
    if (tid >= 1) {
        float a = pw[tid - 1], b = pw[tid], c = pw[tid + 1];
        p3A = a + b + c;
        vA = (b > a) && (b > c) && (p3A > g_athpow[tid]);
    }
    {
        int f = tid + 128;   // 128..255
        float a = pw[f - 1], b = pw[f], c = pw[f + 1];
        p3B = a + b + c;
        vB = (b > a) && (b > c) && (p3B > g_athpow[f]);
    }
    unsigned mA = __ballot_sync(0xFFFFFFFFu, vA);
    unsigned mB = __ballot_sync(0xFFFFFFFFu, vB);
    if (l == 0) { cnt[w] = __popc(mA); cnt[4 + w] = __popc(mB); }
    __syncthreads();
    if (tid == 0) {
        int s = 0;
        for (int c = 0; c < 8; c++) { cbase[c] = s; s += cnt[c]; }
        nsh = s;
    }
    __syncthreads();
    unsigned below = (1u << l) - 1u;
    if (vA) {
        int pos = cbase[w] + __popc(mA & below);
        order[pos] = (short)tid;
        mcv[pos]   = DB2 * lg2(p3A);
    }
    if (vB) {
        int pos = cbase[4 + w] + __popc(mB & below);
        order[pos] = (short)(tid + 128);
        mcv[pos]   = DB2 * lg2(p3B);
    }
    __syncthreads();

    // faithful sequential dedup (bark by LIST POSITION via lim[] table)
    if (tid == 0) {
        int n = nsh;
        if (n > 1) {
            int ip = 0, lp = slim[0];
            float mip = mcv[0];
            float mi_next = mcv[1];
            for (int i = 1; i < n; i++) {
                float mi = mi_next;
                if (i + 1 < n) mi_next = mcv[i + 1];
                if (i <= lp) {                 // close
                    if (mip < mi) {
                        keepf[ip] = 0;
                        ip++;
                        mip = mcv[ip];
                        lp  = slim[ip];
                    } else {
                        keepf[i] = 0;
                    }
                } else {
                    ip = i; mip = mi; lp = slim[i];
                }
            }
        }
    }
    __syncthreads();

    // warp 0: compact kept maskers, mark bins, parallel suffix sums (double)
    if (tid < 32) {
        int n = nsh, basep = 0;
        for (int c0 = 0; c0 < n; c0 += 32) {
            int i = c0 + tid;
            bool ok = (i < n) && keepf[i];
            unsigned m = __ballot_sync(0xFFFFFFFFu, ok);
            if (ok) {
                int pos = basep + __popc(m & ((1u << tid) - 1u));
                int o = order[i];
                float mv = mcv[i];
                mark[o]  = 1;
                msk[pos] = make_float4(sb[o], (mv + g_dshift[o]) * LG,
                                       fmaf(0.37f, fmaxf(mv - 40.f, 0.f), -27.f) * LG,
                                       0.f);
            }
            basep += __popc(m);
        }
        int K = basep;
        if (tid == 0) Ksh = K;
        // suffix sums of 2^(mb2 - SLP*mz) in double, high chunk first
        double carry = 0.0;
        if (K > 0) {
            for (int c0 = ((K - 1) >> 5) << 5; c0 >= 0; c0 -= 32) {
                int idx = c0 + tid;
                double p = 0.0;
                if (idx < K) {
                    float4 m4 = msk[idx];
                    float e = fmaf(-SLP, m4.x, m4.y);
                    float ei = floorf(e);
                    p = scalbn((double)ex2(e - ei), (int)ei);
                }
#pragma unroll
                for (int o = 1; o < 32; o <<= 1) {
                    double v = __shfl_down_sync(0xFFFFFFFFu, p, o);
                    if (tid + o < 32) p += v;
                }
                p += carry;
                if (idx < K) {
                    int ex; double mant = frexp(p, &ex);
                    um[idx] = make_float2((float)mant, (float)ex);
                }
                carry = __shfl_sync(0xFFFFFFFFu, p, 0);
            }
        }
        if (tid == 0) um[K] = make_float2(0.f, -1e30f);
    }
    __syncthreads();

    // exclusive prefix count of masker bins -> cum[f] = #maskers with bin < f
    {
        int v0 = mark[2 * tid], v1 = mark[2 * tid + 1];
        int s2 = v0 + v1;
        int incl = s2;
#pragma unroll
        for (int o = 1; o < 32; o <<= 1) {
            int u = __shfl_up_sync(0xFFFFFFFFu, incl, o);
            if (l >= o) incl += u;
        }
        if (l == 31) cnt[w] = incl;
        __syncthreads();
        if (tid == 0) {
            int b = 0;
            for (int c = 0; c < 4; c++) { cbase[c] = b; b += cnt[c]; }
        }
        __syncthreads();
        int excl = cbase[w] + incl - s2;
        cum[2 * tid]     = (short)excl;
        cum[2 * tid + 1] = (short)(excl + v0);
        if (tid == 0) cum[256] = (short)Ksh;
    }
    __syncthreads();

    const float* pdp = g_pdel + t * F;
    float lsum = 0.f;
    for (int f = tid; f < F; f += 128) {
        float bf = sb[f];
        int j0 = cum[f];
        int ks = cum[g_bstart[f]];   // maskers >8 bark below: negligible, skip
        float sum = g_athpow[f];
        for (int kk = ks; kk < j0; kk++) {
            float4 m4 = msk[kk];
            sum += ex2(fmaf(m4.z, bf - m4.x, m4.y));
        }
        float2 u = um[j0];
        sum += u.x * ex2(fmaf(SLP, bf, u.y));
        float v = fmaf(SC, pdp[f], -sum);
        if (v > 0.f) lsum += v;
    }
#pragma unroll
    for (int o = 16; o > 0; o >>= 1)
        lsum += __shfl_xor_sync(0xFFFFFFFFu, lsum, o);
    if (l == 0) red[w] = lsum;
    __syncthreads();
    if (tid == 0) {
        g_lpart[t] = red[0] + red[1] + red[2] + red[3];
        __threadfence();
        unsigned d = atomicAdd(&g_ctl.done, 1u);
        slast = (d == (unsigned)(gridDim.x - 1)) ? 1 : 0;
    }
    __syncthreads();
    if (slast) {
        __threadfence();
        double local = 0.0;
        for (int i = tid; i < T; i += 128) local += (double)g_lpart[i];
#pragma unroll
        for (int o = 16; o > 0; o >>= 1)
            local += __shfl_xor_sync(0xFFFFFFFFu, local, o);
        if (l == 0) dred[w] = local;
        __syncthreads();
        if (tid == 0) {
            double acc = dred[0] + dred[1] + dred[2] + dred[3];
            out[0] = (float)(1e-6 * acc / (double)N);
        }
        // self-reset for next graph replay (ordered by kernel boundary)
        if (tid < 64) g_ctl.pmax[tid] = 0u;
        if (tid == 0) g_ctl.done = 0u;
    }
}

// ---------------------------------------------------------------------------
extern "C" void kernel_launch(void* const* d_in, const int* in_sizes, int n_in,
                              void* d_out, int out_size)
{
    const float* xadv = (const float*)d_in[0];
    const float* xref = (const float*)d_in[1];
    float* out = (float*)d_out;

    int L = in_sizes[0];
    int T = (L - W) / HOP + 1;
    if (T > MAXT) T = MAXT;
    int N  = T * F;
    int Lv = (T - 1) * HOP + W;
    int ng = (T + FT - 1) / FT;

    stft_kernel<<<dim3(ng, 3), 128>>>(xadv, xref, T, Lv);
    thresh_kernel<<<T, 128>>>(out, T, N);
}